// round 13
// baseline (speedup 1.0000x reference)
#include <cuda_runtime.h>
#include <cuda_fp16.h>
#include <cstdint>
#include <math.h>

// LSTM_2370821948014 — round 12: R12 + intra-tile software pipelining.
// Each 64-k tile = 8 stages (4 k-steps x 2 nt-halves); fragments double-
// buffered so stage s+1's ldmatrix ops are in flight during stage s's MMAs.
// MT=128 rows/CTA (512 CTAs), 30 tiles of 256 rows x 64 k fp16 (32KB),
// NBUF=3, per-warp producer/consumer mbarriers (no per-tile CTA barriers).
// 16 warps as 4M x 4N, warp tile 32x64, mma.sync.m16n8k16.f16.

static constexpr int BATCH = 65536;
static constexpr int ODIM  = 256;
static constexpr int KDIM  = 384;
static constexpr int MT    = 128;
static constexpr int THREADS = 512;
static constexpr int NBUF = 3;
static constexpr int NTILES  = 30;        // 5 chunks x 6 k-tiles (k=64)
static constexpr int TILE_U32 = 8192;     // 256 rows x 32 words (32KB)

// SMEM layout (bytes)
static constexpr int PA2     = 196;                 // A pitch (u32, fp16 pairs)
static constexpr int SM_A    = 0;                   // 128*196*4 = 100352
static constexpr int SM_W    = 100352;              // 3 x 32768
static constexpr int WB      = 32768;
static constexpr int SM_BIAS = SM_W + NBUF * WB;    // 198656 (1280 floats)
static constexpr int SM_REDM = SM_BIAS + 5120;      // 203776
static constexpr int SM_REDS = SM_REDM + 2048;      // 205824
static constexpr int SM_MB   = SM_REDS + 2048;      // 207872: full[3] cons[3]
static constexpr int SMEM_TOTAL = SM_MB + 64;       // 207936

__device__ uint32_t w_packed[NTILES * TILE_U32];    // ~0.98MB scratch

// ---------------- helpers ----------------

__device__ __forceinline__ uint32_t smem_u32(const void* p) {
    uint32_t a;
    asm("{ .reg .u64 t; cvta.to.shared.u64 t, %1; cvt.u32.u64 %0, t; }"
        : "=r"(a) : "l"(p));
    return a;
}

__device__ __forceinline__ uint32_t pack_h2(float x, float y) {
    __half2 h = __floats2half2_rn(x, y);
    return *reinterpret_cast<uint32_t*>(&h);
}

__device__ __forceinline__ void mbar_init(uint32_t a, uint32_t cnt) {
    asm volatile("mbarrier.init.shared.b64 [%0], %1;" :: "r"(a), "r"(cnt) : "memory");
}

__device__ __forceinline__ void mbar_expect_tx(uint32_t a, uint32_t bytes) {
    asm volatile("mbarrier.arrive.expect_tx.shared.b64 _, [%0], %1;"
                 :: "r"(a), "r"(bytes) : "memory");
}

__device__ __forceinline__ void mbar_arrive(uint32_t a) {
    asm volatile("mbarrier.arrive.shared.b64 _, [%0];" :: "r"(a) : "memory");
}

__device__ __forceinline__ void mbar_wait(uint32_t a, uint32_t parity) {
    asm volatile(
        "{\n\t"
        ".reg .pred P;\n\t"
        "W%=:\n\t"
        "mbarrier.try_wait.parity.acquire.cta.shared::cta.b64 P, [%0], %1, 0x989680;\n\t"
        "@P bra D%=;\n\t"
        "bra W%=;\n\t"
        "D%=:\n\t"
        "}"
        :: "r"(a), "r"(parity) : "memory");
}

__device__ __forceinline__ void bulk_ld(uint32_t dst, const void* src,
                                        uint32_t bytes, uint32_t mbar) {
    asm volatile(
        "cp.async.bulk.shared::cluster.global.mbarrier::complete_tx::bytes "
        "[%0], [%1], %2, [%3];"
        :: "r"(dst), "l"(src), "r"(bytes), "r"(mbar) : "memory");
}

__device__ __forceinline__ void ldsm4(uint32_t* r, uint32_t addr) {
    asm volatile(
        "ldmatrix.sync.aligned.m8n8.x4.shared.b16 {%0,%1,%2,%3}, [%4];"
        : "=r"(r[0]), "=r"(r[1]), "=r"(r[2]), "=r"(r[3]) : "r"(addr));
}

__device__ __forceinline__ void mma16(float* d, const uint32_t* a,
                                      uint32_t b0, uint32_t b1) {
    asm volatile(
        "mma.sync.aligned.m16n8k16.row.col.f32.f16.f16.f32 "
        "{%0,%1,%2,%3}, {%4,%5,%6,%7}, {%8,%9}, {%0,%1,%2,%3};"
        : "+f"(d[0]), "+f"(d[1]), "+f"(d[2]), "+f"(d[3])
        : "r"(a[0]), "r"(a[1]), "r"(a[2]), "r"(a[3]), "r"(b0), "r"(b1));
}

__device__ __forceinline__ float sigf(float x) {
    return 1.0f / (1.0f + __expf(-x));
}
__device__ __forceinline__ float tanh_fast(float x) {
    x = fminf(fmaxf(x, -15.0f), 15.0f);
    float e = __expf(2.0f * x);
    return (e - 1.0f) / (e + 1.0f);
}

// ---------------- repack kernel ----------------
// tile t = chunk*6 + kt (k window 64).  Gates chunks (0..3): tile row
//   v = wn*64 + (g*2+jh)*8 + jlo -> w_i2h row g*256 + chunk*64 + wn*16 +
//   jh*8 + jlo.  Logits chunk (4): row v -> w_i2o row v.
// Row v holds 32 fp16-pair words (k = kt*64 + 2w). 16B-chunk swizzle:
//   stored u32 index = v*32 + (((w>>2) ^ (v&7)) << 2) + (w&3).

__global__ void repack_kernel(const float* __restrict__ w_i2h,
                              const float* __restrict__ w_i2o)
{
    int i = blockIdx.x * 256 + threadIdx.x;
    if (i >= NTILES * TILE_U32) return;
    int t  = i / TILE_U32;
    int e  = i - t * TILE_U32;
    int v  = e >> 5;
    int w  = e & 31;
    int chunk = t / 6;
    int kt    = t - chunk * 6;
    const float* src;
    int row;
    if (chunk < 4) {
        int wn  = v >> 6;
        int nt  = (v >> 3) & 7;
        int jlo = v & 7;
        int g   = nt >> 1;
        int jh  = nt & 1;
        row = g * 256 + chunk * 64 + wn * 16 + jh * 8 + jlo;
        src = w_i2h;
    } else {
        row = v;
        src = w_i2o;
    }
    const float* p = src + (size_t)row * KDIM + kt * 64 + w * 2;
    w_packed[t * TILE_U32 + v * 32 + (((w >> 2) ^ (v & 7)) << 2) + (w & 3)] =
        pack_h2(p[0], p[1]);
}

// ---------------- main kernel ----------------

__global__ __launch_bounds__(THREADS, 1)
void lstm_mma_kernel(const float* __restrict__ input,
                     const float* __restrict__ hidden,
                     const float* __restrict__ b_i2h,
                     const float* __restrict__ b_i2o,
                     float* __restrict__ out)
{
    extern __shared__ char smem[];
    const uint32_t sbase = smem_u32(smem);
    const int tid  = threadIdx.x;
    const int wid  = tid >> 5;
    const int lane = tid & 31;
    const int wm   = wid >> 2;          // 0..3 (M)
    const int wn   = wid & 3;           // 0..3 (N)
    const int gID  = lane >> 2;         // 0..7
    const int lq   = lane & 3;          // 0..3
    const int rbase = blockIdx.x * MT;
    const bool isProd = (tid == 0);

    uint32_t* Au2 = (uint32_t*)(smem + SM_A);
    float*    bias = (float*)(smem + SM_BIAS);
    const uint32_t fullB = sbase + SM_MB;        // 3 x 8B
    const uint32_t consB = sbase + SM_MB + 24;   // 3 x 8B

    // ldmatrix A: matrix q (lanes 8q..8q+7): rows +8*(q&1), k-half (q>>1)
    const int aRow  = wm * 32 + (lane & 7) + 8 * ((lane >> 3) & 1);
    const int aKsel = 4 * ((lane >> 4) & 1);           // 16B chunk (k0/k8)
    const uint32_t aBase0 = sbase + SM_A + (uint32_t)(aRow * PA2 + aKsel) * 4;
    const uint32_t aBase1 = aBase0 + 16 * PA2 * 4;

    // ldmatrix B: pair p covers nt {2p,2p+1}; rows bRowBase + 16p.
    const int bKb      = (lane >> 3) & 1;
    const int bRowBase = wn * 64 + 8 * ((lane >> 4) & 1) + (lane & 7);
    const int bMask    = bRowBase & 7;     // +16p,+8 keep (row&7)
    const uint32_t bOff0 = (uint32_t)bRowBase * 128;
    const uint32_t bOff1 = bOff0 + 16 * 128;
    const uint32_t bOff2 = bOff0 + 32 * 128;
    const uint32_t bOff3 = bOff0 + 48 * 128;

    if (tid == 0) {
        for (int b = 0; b < NBUF; ++b) {
            mbar_init(fullB + 8 * b, 1);
            mbar_init(consB + 8 * b, 16);
        }
    }
    __syncthreads();

    // prologue: load tiles 0,1,2 (overlaps A/bias staging)
    if (isProd) {
        for (int u = 0; u < NBUF; ++u) {
            mbar_expect_tx(fullB + 8 * u, WB);
            bulk_ld(sbase + SM_W + u * WB, w_packed + (size_t)u * TILE_U32,
                    WB, fullB + 8 * u);
        }
    }

    // stage A (fp16 pairs, pitch 196 u32)
    for (int idx = tid; idx < MT * 96; idx += THREADS) {
        int r  = idx / 96;
        int c4 = idx - r * 96;
        float4 v = (c4 < 32)
            ? *(const float4*)(input  + (size_t)(rbase + r) * 128 + c4 * 4)
            : *(const float4*)(hidden + (size_t)(rbase + r) * 256 + (c4 - 32) * 4);
        uint2 u;
        u.x = pack_h2(v.x, v.y);
        u.y = pack_h2(v.z, v.w);
        *(uint2*)(Au2 + r * PA2 + c4 * 2) = u;
    }
    for (int i = tid; i < 1280; i += THREADS)
        bias[i] = (i < 1024) ? b_i2h[i] : b_i2o[i - 1024];
    __syncthreads();   // A/bias visible to all warps before fragment reads

    float* outLS = out;
    float* outNH = out + (size_t)BATCH * ODIM;

    float acc[2][8][4];
    #pragma unroll
    for (int m = 0; m < 2; ++m)
        #pragma unroll
        for (int n = 0; n < 8; ++n)
            #pragma unroll
            for (int c = 0; c < 4; ++c) acc[m][n][c] = 0.0f;

    for (int t = 0; t < NTILES; ++t) {
        const int buf = t % NBUF;
        mbar_wait(fullB + 8 * buf, (t / NBUF) & 1);

        const uint32_t Wbase = sbase + SM_W + buf * WB;
        const uint32_t aK = (uint32_t)((t % 6) * 128);   // A byte base (k=64)

        // ---- software-pipelined 8 stages (4 ks x 2 halves) ----
        uint32_t af[2][8], bf[2][8];
        // stage 0 prologue
        ldsm4(af[0] + 0, aBase0 + aK);
        ldsm4(af[0] + 4, aBase1 + aK);
        {
            const uint32_t c = (uint32_t)((bKb ^ bMask) << 4);
            ldsm4(bf[0] + 0, Wbase + bOff0 + c);
            ldsm4(bf[0] + 4, Wbase + bOff1 + c);
        }
        #pragma unroll
        for (int s = 0; s < 8; ++s) {
            const int ks   = s >> 1;
            const int half = s & 1;
            const uint32_t* A = af[ks & 1];
            const uint32_t* B = bf[s & 1];
            // prefetch stage s+1 into the other buffers
            if (s < 7) {
                const int ns  = s + 1;
                const int nks = ns >> 1;
                const int nh  = ns & 1;
                const uint32_t nc = (uint32_t)(((2 * nks + bKb) ^ bMask) << 4);
                if (nh == 0) {
                    ldsm4(af[nks & 1] + 0, aBase0 + aK + nks * 32);
                    ldsm4(af[nks & 1] + 4, aBase1 + aK + nks * 32);
                    ldsm4(bf[ns & 1] + 0, Wbase + bOff0 + nc);
                    ldsm4(bf[ns & 1] + 4, Wbase + bOff1 + nc);
                } else {
                    ldsm4(bf[ns & 1] + 0, Wbase + bOff2 + nc);
                    ldsm4(bf[ns & 1] + 4, Wbase + bOff3 + nc);
                }
            }
            // 8 MMAs for this stage: acc pairs q..q+1 (ldsm0), q+2..q+3 (ldsm1)
            const int q = half * 4;
            mma16(acc[0][q + 0], A,     B[0], B[1]);
            mma16(acc[1][q + 0], A + 4, B[0], B[1]);
            mma16(acc[0][q + 1], A,     B[2], B[3]);
            mma16(acc[1][q + 1], A + 4, B[2], B[3]);
            mma16(acc[0][q + 2], A,     B[4], B[5]);
            mma16(acc[1][q + 2], A + 4, B[4], B[5]);
            mma16(acc[0][q + 3], A,     B[6], B[7]);
            mma16(acc[1][q + 3], A + 4, B[6], B[7]);
        }

        // this warp is done with buffer buf
        if (lane == 0) mbar_arrive(consB + 8 * buf);

        // producer: once ALL warps have consumed tile t, reload buf for t+3
        if (isProd && t + NBUF < NTILES) {
            mbar_wait(consB + 8 * buf, (t / NBUF) & 1);
            mbar_expect_tx(fullB + 8 * buf, WB);
            bulk_ld(sbase + SM_W + buf * WB,
                    w_packed + (size_t)(t + NBUF) * TILE_U32, WB,
                    fullB + 8 * buf);
        }

        if ((t % 6) == 5) {
            const int chunk = t / 6;
            if (chunk < 4) {
                // ---- LSTM epilogue: nt = g*2+jh, all gates in-register ----
                #pragma unroll
                for (int mt = 0; mt < 2; ++mt)
                    #pragma unroll
                    for (int rh = 0; rh < 2; ++rh)
                        #pragma unroll
                        for (int jh = 0; jh < 2; ++jh) {
                            int r  = wm * 32 + mt * 16 + rh * 8 + gID;
                            int j0 = chunk * 64 + wn * 16 + jh * 8 + lq * 2;
                            int ci = rh * 2;
                            float h0 = acc[mt][jh][ci]     + bias[j0];
                            float h1 = acc[mt][jh][ci+1]   + bias[j0+1];
                            float i0 = acc[mt][2+jh][ci]   + bias[256+j0];
                            float i1 = acc[mt][2+jh][ci+1] + bias[256+j0+1];
                            float f0 = acc[mt][4+jh][ci]   + bias[512+j0];
                            float f1 = acc[mt][4+jh][ci+1] + bias[512+j0+1];
                            float o0 = acc[mt][6+jh][ci]   + bias[768+j0];
                            float o1 = acc[mt][6+jh][ci+1] + bias[768+j0+1];
                            float2 hv = *(const float2*)(
                                hidden + (size_t)(rbase + r) * 256 + j0);
                            float2 nh;
                            nh.x = sigf(o0) * tanh_fast(sigf(f0) * hv.x + sigf(i0) * tanh_fast(h0));
                            nh.y = sigf(o1) * tanh_fast(sigf(f1) * hv.y + sigf(i1) * tanh_fast(h1));
                            *(float2*)(outNH + (size_t)(rbase + r) * 256 + j0) = nh;
                        }
                #pragma unroll
                for (int m = 0; m < 2; ++m)
                    #pragma unroll
                    for (int n = 0; n < 8; ++n)
                        #pragma unroll
                        for (int c = 0; c < 4; ++c) acc[m][n][c] = 0.0f;
            } else {
                // ---- logits epilogue: log_softmax over 256 cols ----
                float* redm = (float*)(smem + SM_REDM);
                float* reds = (float*)(smem + SM_REDS);

                #pragma unroll
                for (int mt = 0; mt < 2; ++mt)
                    #pragma unroll
                    for (int nt = 0; nt < 8; ++nt) {
                        int n0 = wn * 64 + nt * 8 + lq * 2;
                        acc[mt][nt][0] += bias[1024 + n0];
                        acc[mt][nt][1] += bias[1024 + n0 + 1];
                        acc[mt][nt][2] += bias[1024 + n0];
                        acc[mt][nt][3] += bias[1024 + n0 + 1];
                    }

                #pragma unroll
                for (int mt = 0; mt < 2; ++mt)
                    #pragma unroll
                    for (int rh = 0; rh < 2; ++rh) {
                        float m = -3.4e38f;
                        #pragma unroll
                        for (int nt = 0; nt < 8; ++nt) {
                            m = fmaxf(m, acc[mt][nt][rh*2]);
                            m = fmaxf(m, acc[mt][nt][rh*2+1]);
                        }
                        m = fmaxf(m, __shfl_xor_sync(0xffffffffu, m, 1));
                        m = fmaxf(m, __shfl_xor_sync(0xffffffffu, m, 2));
                        if (lq == 0) {
                            int r = wm * 32 + mt * 16 + rh * 8 + gID;
                            redm[r * 4 + wn] = m;
                        }
                    }
                __syncthreads();

                float M[2][2], L[2][2];
                #pragma unroll
                for (int mt = 0; mt < 2; ++mt)
                    #pragma unroll
                    for (int rh = 0; rh < 2; ++rh) {
                        int r = wm * 32 + mt * 16 + rh * 8 + gID;
                        const float* rm = redm + r * 4;
                        float m = fmaxf(fmaxf(rm[0], rm[1]),
                                        fmaxf(rm[2], rm[3]));
                        M[mt][rh] = m;
                        float s = 0.0f;
                        #pragma unroll
                        for (int nt = 0; nt < 8; ++nt) {
                            s += __expf(acc[mt][nt][rh*2]   - m);
                            s += __expf(acc[mt][nt][rh*2+1] - m);
                        }
                        s += __shfl_xor_sync(0xffffffffu, s, 1);
                        s += __shfl_xor_sync(0xffffffffu, s, 2);
                        if (lq == 0) reds[r * 4 + wn] = s;
                    }
                __syncthreads();

                #pragma unroll
                for (int mt = 0; mt < 2; ++mt)
                    #pragma unroll
                    for (int rh = 0; rh < 2; ++rh) {
                        int r = wm * 32 + mt * 16 + rh * 8 + gID;
                        const float* rs = reds + r * 4;
                        float st = (rs[0] + rs[1]) + (rs[2] + rs[3]);
                        L[mt][rh] = M[mt][rh] + logf(st);
                    }

                #pragma unroll
                for (int mt = 0; mt < 2; ++mt)
                    #pragma unroll
                    for (int rh = 0; rh < 2; ++rh) {
                        int r = wm * 32 + mt * 16 + rh * 8 + gID;
                        float lse = L[mt][rh];
                        #pragma unroll
                        for (int nt = 0; nt < 8; ++nt) {
                            int n0 = wn * 64 + nt * 8 + lq * 2;
                            float2 o;
                            o.x = acc[mt][nt][rh*2]   - lse;
                            o.y = acc[mt][nt][rh*2+1] - lse;
                            *(float2*)(outLS + (size_t)(rbase + r) * 256 + n0) = o;
                        }
                    }
            }
        }
    }
}

extern "C" void kernel_launch(void* const* d_in, const int* in_sizes, int n_in,
                              void* d_out, int out_size)
{
    (void)in_sizes; (void)n_in; (void)out_size;
    const float* input  = (const float*)d_in[0];
    const float* hidden = (const float*)d_in[1];
    const float* w_i2h  = (const float*)d_in[2];
    const float* b_i2h  = (const float*)d_in[3];
    const float* w_i2o  = (const float*)d_in[4];
    const float* b_i2o  = (const float*)d_in[5];
    float* out = (float*)d_out;

    repack_kernel<<<(NTILES * TILE_U32 + 255) / 256, 256>>>(w_i2h, w_i2o);

    cudaFuncSetAttribute(lstm_mma_kernel,
                         cudaFuncAttributeMaxDynamicSharedMemorySize,
                         SMEM_TOTAL);
    lstm_mma_kernel<<<BATCH / MT, THREADS, SMEM_TOTAL>>>(
        input, hidden, b_i2h, b_i2o, out);
}

// round 14
// speedup vs baseline: 1.0030x; 1.0030x over previous
#include <cuda_runtime.h>
#include <cuda_fp16.h>
#include <cstdint>
#include <math.h>

// LSTM_2370821948014 — round 13: 2 CTAs/SM. MT=64 rows/CTA (1024 CTAs),
// 256 threads (8 warps as 2M x 4N, warp tile 32x64), per-CTA smem ~101KB so
// two CTAs co-reside (occ 50%). 60 W tiles of 128 rows x 64 k fp16 (16KB),
// NBUF=3; tile parity selects which N-half of warps is active (inactive
// warps just arrive). Biases from gmem. Inner loop = proven R11 shape.

static constexpr int BATCH = 65536;
static constexpr int ODIM  = 256;
static constexpr int KDIM  = 384;
static constexpr int MT    = 64;
static constexpr int THREADS = 256;
static constexpr int NBUF = 3;
static constexpr int NTILES  = 60;        // 5 chunks x 6 kt x 2 halves
static constexpr int TILE_U32 = 4096;     // 128 rows x 32 words (16KB)

// SMEM layout (bytes), per CTA
static constexpr int PA2     = 196;                 // A pitch (u32, fp16 pairs)
static constexpr int SM_A    = 0;                   // 64*196*4 = 50176
static constexpr int SM_W    = 50176;               // 3 x 16384 = 49152
static constexpr int WB      = 16384;
static constexpr int SM_REDM = SM_W + NBUF * WB;    // 99328 (256 floats)
static constexpr int SM_REDS = SM_REDM + 1024;      // 100352
static constexpr int SM_MB   = SM_REDS + 1024;      // 101376: full[3] cons[3]
static constexpr int SMEM_TOTAL = SM_MB + 64;       // 101440

__device__ uint32_t w_packed[NTILES * TILE_U32];    // ~0.98MB scratch

// ---------------- helpers ----------------

__device__ __forceinline__ uint32_t smem_u32(const void* p) {
    uint32_t a;
    asm("{ .reg .u64 t; cvta.to.shared.u64 t, %1; cvt.u32.u64 %0, t; }"
        : "=r"(a) : "l"(p));
    return a;
}

__device__ __forceinline__ uint32_t pack_h2(float x, float y) {
    __half2 h = __floats2half2_rn(x, y);
    return *reinterpret_cast<uint32_t*>(&h);
}

__device__ __forceinline__ void mbar_init(uint32_t a, uint32_t cnt) {
    asm volatile("mbarrier.init.shared.b64 [%0], %1;" :: "r"(a), "r"(cnt) : "memory");
}

__device__ __forceinline__ void mbar_expect_tx(uint32_t a, uint32_t bytes) {
    asm volatile("mbarrier.arrive.expect_tx.shared.b64 _, [%0], %1;"
                 :: "r"(a), "r"(bytes) : "memory");
}

__device__ __forceinline__ void mbar_arrive(uint32_t a) {
    asm volatile("mbarrier.arrive.shared.b64 _, [%0];" :: "r"(a) : "memory");
}

__device__ __forceinline__ void mbar_wait(uint32_t a, uint32_t parity) {
    asm volatile(
        "{\n\t"
        ".reg .pred P;\n\t"
        "W%=:\n\t"
        "mbarrier.try_wait.parity.acquire.cta.shared::cta.b64 P, [%0], %1, 0x989680;\n\t"
        "@P bra D%=;\n\t"
        "bra W%=;\n\t"
        "D%=:\n\t"
        "}"
        :: "r"(a), "r"(parity) : "memory");
}

__device__ __forceinline__ void bulk_ld(uint32_t dst, const void* src,
                                        uint32_t bytes, uint32_t mbar) {
    asm volatile(
        "cp.async.bulk.shared::cluster.global.mbarrier::complete_tx::bytes "
        "[%0], [%1], %2, [%3];"
        :: "r"(dst), "l"(src), "r"(bytes), "r"(mbar) : "memory");
}

__device__ __forceinline__ void ldsm4(uint32_t* r, uint32_t addr) {
    asm volatile(
        "ldmatrix.sync.aligned.m8n8.x4.shared.b16 {%0,%1,%2,%3}, [%4];"
        : "=r"(r[0]), "=r"(r[1]), "=r"(r[2]), "=r"(r[3]) : "r"(addr));
}

__device__ __forceinline__ void mma16(float* d, const uint32_t* a,
                                      uint32_t b0, uint32_t b1) {
    asm volatile(
        "mma.sync.aligned.m16n8k16.row.col.f32.f16.f16.f32 "
        "{%0,%1,%2,%3}, {%4,%5,%6,%7}, {%8,%9}, {%0,%1,%2,%3};"
        : "+f"(d[0]), "+f"(d[1]), "+f"(d[2]), "+f"(d[3])
        : "r"(a[0]), "r"(a[1]), "r"(a[2]), "r"(a[3]), "r"(b0), "r"(b1));
}

__device__ __forceinline__ float sigf(float x) {
    return 1.0f / (1.0f + __expf(-x));
}
__device__ __forceinline__ float tanh_fast(float x) {
    x = fminf(fmaxf(x, -15.0f), 15.0f);
    float e = __expf(2.0f * x);
    return (e - 1.0f) / (e + 1.0f);
}

// ---------------- repack kernel ----------------
// tile t = chunk*12 + kt*2 + half  (kt: 64-k window; half: N-half).
// Gates chunks (0..3): tile row v (0..127): wn = half*2 + (v>>6),
//   nt=(v>>3)&7, jlo=v&7, g=nt>>1, jh=nt&1 ->
//   w_i2h row g*256 + chunk*64 + wn*16 + jh*8 + jlo.
// Logits chunk (4): row = half*128 + v.
// Row v holds 32 fp16-pair words (k = kt*64 + 2w); stored u32 index
//   v*32 + (((w>>2) ^ (v&7)) << 2) + (w&3).

__global__ void repack_kernel(const float* __restrict__ w_i2h,
                              const float* __restrict__ w_i2o)
{
    int i = blockIdx.x * 256 + threadIdx.x;
    if (i >= NTILES * TILE_U32) return;
    int t  = i / TILE_U32;
    int e  = i - t * TILE_U32;
    int v  = e >> 5;
    int w  = e & 31;
    int chunk = t / 12;
    int r12   = t - chunk * 12;
    int kt    = r12 >> 1;
    int half  = r12 & 1;
    const float* src;
    int row;
    if (chunk < 4) {
        int wn  = half * 2 + (v >> 6);
        int nt  = (v >> 3) & 7;
        int jlo = v & 7;
        int g   = nt >> 1;
        int jh  = nt & 1;
        row = g * 256 + chunk * 64 + wn * 16 + jh * 8 + jlo;
        src = w_i2h;
    } else {
        row = half * 128 + v;
        src = w_i2o;
    }
    const float* p = src + (size_t)row * KDIM + kt * 64 + w * 2;
    w_packed[t * TILE_U32 + v * 32 + (((w >> 2) ^ (v & 7)) << 2) + (w & 3)] =
        pack_h2(p[0], p[1]);
}

// ---------------- main kernel ----------------

__global__ __launch_bounds__(THREADS, 2)
void lstm_mma_kernel(const float* __restrict__ input,
                     const float* __restrict__ hidden,
                     const float* __restrict__ b_i2h,
                     const float* __restrict__ b_i2o,
                     float* __restrict__ out)
{
    extern __shared__ char smem[];
    const uint32_t sbase = smem_u32(smem);
    const int tid  = threadIdx.x;
    const int wid  = tid >> 5;
    const int lane = tid & 31;
    const int wm   = wid >> 2;          // 0..1 (M)
    const int wn   = wid & 3;           // 0..3 (N)
    const int gID  = lane >> 2;         // 0..7
    const int lq   = lane & 3;          // 0..3
    const int myHalf = wn >> 1;         // which tile-half this warp consumes
    const int rbase = blockIdx.x * MT;
    const bool isProd = (tid == 0);

    uint32_t* Au2 = (uint32_t*)(smem + SM_A);
    const uint32_t fullB = sbase + SM_MB;        // 3 x 8B
    const uint32_t consB = sbase + SM_MB + 24;   // 3 x 8B

    // ldmatrix A: matrix q (lanes 8q..8q+7): rows +8*(q&1), k-half (q>>1)
    const int aRow  = wm * 32 + (lane & 7) + 8 * ((lane >> 3) & 1);
    const int aKsel = 4 * ((lane >> 4) & 1);
    const uint32_t aBase0 = sbase + SM_A + (uint32_t)(aRow * PA2 + aKsel) * 4;
    const uint32_t aBase1 = aBase0 + 16 * PA2 * 4;

    // ldmatrix B: within 128-row tile, this warp's rows start (wn&1)*64.
    const int bKb      = (lane >> 3) & 1;
    const int bRowBase = (wn & 1) * 64 + 8 * ((lane >> 4) & 1) + (lane & 7);
    const int bMask    = bRowBase & 7;
    const uint32_t bOff0 = (uint32_t)bRowBase * 128;
    const uint32_t bOff1 = bOff0 + 16 * 128;
    const uint32_t bOff2 = bOff0 + 32 * 128;
    const uint32_t bOff3 = bOff0 + 48 * 128;

    if (tid == 0) {
        for (int b = 0; b < NBUF; ++b) {
            mbar_init(fullB + 8 * b, 1);
            mbar_init(consB + 8 * b, 8);
        }
    }
    __syncthreads();

    // prologue: load tiles 0,1,2 (overlaps A staging)
    if (isProd) {
        for (int u = 0; u < NBUF; ++u) {
            mbar_expect_tx(fullB + 8 * u, WB);
            bulk_ld(sbase + SM_W + u * WB, w_packed + (size_t)u * TILE_U32,
                    WB, fullB + 8 * u);
        }
    }

    // stage A (fp16 pairs, pitch 196 u32)
    for (int idx = tid; idx < MT * 96; idx += THREADS) {
        int r  = idx / 96;
        int c4 = idx - r * 96;
        float4 v = (c4 < 32)
            ? *(const float4*)(input  + (size_t)(rbase + r) * 128 + c4 * 4)
            : *(const float4*)(hidden + (size_t)(rbase + r) * 256 + (c4 - 32) * 4);
        uint2 u;
        u.x = pack_h2(v.x, v.y);
        u.y = pack_h2(v.z, v.w);
        *(uint2*)(Au2 + r * PA2 + c4 * 2) = u;
    }
    __syncthreads();

    float* outLS = out;
    float* outNH = out + (size_t)BATCH * ODIM;

    float acc[2][8][4];
    #pragma unroll
    for (int m = 0; m < 2; ++m)
        #pragma unroll
        for (int n = 0; n < 8; ++n)
            #pragma unroll
            for (int c = 0; c < 4; ++c) acc[m][n][c] = 0.0f;

    for (int t = 0; t < NTILES; ++t) {
        const int buf = t % NBUF;
        mbar_wait(fullB + 8 * buf, (t / NBUF) & 1);

        if ((t & 1) == myHalf) {
            const uint32_t Wbase = sbase + SM_W + buf * WB;
            const int kt = (t % 12) >> 1;
            const uint32_t aK = (uint32_t)(kt * 128);   // A byte base (k=64)

            #pragma unroll
            for (int ks = 0; ks < 4; ++ks) {
                uint32_t a0[4], a1[4], b[16];
                const uint32_t aoff = aK + ks * 32;
                ldsm4(a0, aBase0 + aoff);
                ldsm4(a1, aBase1 + aoff);
                const uint32_t c = (uint32_t)(((2 * ks + bKb) ^ bMask) << 4);
                ldsm4(b + 0,  Wbase + bOff0 + c);   // nt 0,1
                ldsm4(b + 4,  Wbase + bOff1 + c);   // nt 2,3
                ldsm4(b + 8,  Wbase + bOff2 + c);   // nt 4,5
                ldsm4(b + 12, Wbase + bOff3 + c);   // nt 6,7
                #pragma unroll
                for (int p = 0; p < 4; ++p) {
                    mma16(acc[0][2*p],   a0, b[4*p],   b[4*p+1]);
                    mma16(acc[1][2*p],   a1, b[4*p],   b[4*p+1]);
                    mma16(acc[0][2*p+1], a0, b[4*p+2], b[4*p+3]);
                    mma16(acc[1][2*p+1], a1, b[4*p+2], b[4*p+3]);
                }
            }
        }

        if (lane == 0) mbar_arrive(consB + 8 * buf);

        if (isProd && t + NBUF < NTILES) {
            mbar_wait(consB + 8 * buf, (t / NBUF) & 1);
            mbar_expect_tx(fullB + 8 * buf, WB);
            bulk_ld(sbase + SM_W + buf * WB,
                    w_packed + (size_t)(t + NBUF) * TILE_U32, WB,
                    fullB + 8 * buf);
        }

        if ((t % 12) == 11) {
            const int chunk = t / 12;
            if (chunk < 4) {
                // ---- LSTM epilogue: nt = g*2+jh, gates in-register ----
                #pragma unroll
                for (int mt = 0; mt < 2; ++mt)
                    #pragma unroll
                    for (int rh = 0; rh < 2; ++rh)
                        #pragma unroll
                        for (int jh = 0; jh < 2; ++jh) {
                            int r  = wm * 32 + mt * 16 + rh * 8 + gID;
                            int j0 = chunk * 64 + wn * 16 + jh * 8 + lq * 2;
                            int ci = rh * 2;
                            float h0 = acc[mt][jh][ci]     + b_i2h[j0];
                            float h1 = acc[mt][jh][ci+1]   + b_i2h[j0+1];
                            float i0 = acc[mt][2+jh][ci]   + b_i2h[256+j0];
                            float i1 = acc[mt][2+jh][ci+1] + b_i2h[256+j0+1];
                            float f0 = acc[mt][4+jh][ci]   + b_i2h[512+j0];
                            float f1 = acc[mt][4+jh][ci+1] + b_i2h[512+j0+1];
                            float o0 = acc[mt][6+jh][ci]   + b_i2h[768+j0];
                            float o1 = acc[mt][6+jh][ci+1] + b_i2h[768+j0+1];
                            float2 hv = *(const float2*)(
                                hidden + (size_t)(rbase + r) * 256 + j0);
                            float2 nh;
                            nh.x = sigf(o0) * tanh_fast(sigf(f0) * hv.x + sigf(i0) * tanh_fast(h0));
                            nh.y = sigf(o1) * tanh_fast(sigf(f1) * hv.y + sigf(i1) * tanh_fast(h1));
                            *(float2*)(outNH + (size_t)(rbase + r) * 256 + j0) = nh;
                        }
                #pragma unroll
                for (int m = 0; m < 2; ++m)
                    #pragma unroll
                    for (int n = 0; n < 8; ++n)
                        #pragma unroll
                        for (int c = 0; c < 4; ++c) acc[m][n][c] = 0.0f;
            } else {
                // ---- logits epilogue: log_softmax over 256 cols ----
                // warp covers cols nBase + nt*8 (+2 of lq*2)
                const int nBase = myHalf * 128 + (wn & 1) * 64;
                float* redm = (float*)(smem + SM_REDM);
                float* reds = (float*)(smem + SM_REDS);

                #pragma unroll
                for (int mt = 0; mt < 2; ++mt)
                    #pragma unroll
                    for (int nt = 0; nt < 8; ++nt) {
                        int n0 = nBase + nt * 8 + lq * 2;
                        float bz0 = b_i2o[n0], bz1 = b_i2o[n0 + 1];
                        acc[mt][nt][0] += bz0;
                        acc[mt][nt][1] += bz1;
                        acc[mt][nt][2] += bz0;
                        acc[mt][nt][3] += bz1;
                    }

                #pragma unroll
                for (int mt = 0; mt < 2; ++mt)
                    #pragma unroll
                    for (int rh = 0; rh < 2; ++rh) {
                        float m = -3.4e38f;
                        #pragma unroll
                        for (int nt = 0; nt < 8; ++nt) {
                            m = fmaxf(m, acc[mt][nt][rh*2]);
                            m = fmaxf(m, acc[mt][nt][rh*2+1]);
                        }
                        m = fmaxf(m, __shfl_xor_sync(0xffffffffu, m, 1));
                        m = fmaxf(m, __shfl_xor_sync(0xffffffffu, m, 2));
                        if (lq == 0) {
                            int r = wm * 32 + mt * 16 + rh * 8 + gID;
                            redm[r * 4 + wn] = m;
                        }
                    }
                __syncthreads();

                float M[2][2], L[2][2];
                #pragma unroll
                for (int mt = 0; mt < 2; ++mt)
                    #pragma unroll
                    for (int rh = 0; rh < 2; ++rh) {
                        int r = wm * 32 + mt * 16 + rh * 8 + gID;
                        const float* rm = redm + r * 4;
                        float m = fmaxf(fmaxf(rm[0], rm[1]),
                                        fmaxf(rm[2], rm[3]));
                        M[mt][rh] = m;
                        float s = 0.0f;
                        #pragma unroll
                        for (int nt = 0; nt < 8; ++nt) {
                            s += __expf(acc[mt][nt][rh*2]   - m);
                            s += __expf(acc[mt][nt][rh*2+1] - m);
                        }
                        s += __shfl_xor_sync(0xffffffffu, s, 1);
                        s += __shfl_xor_sync(0xffffffffu, s, 2);
                        if (lq == 0) reds[r * 4 + wn] = s;
                    }
                __syncthreads();

                #pragma unroll
                for (int mt = 0; mt < 2; ++mt)
                    #pragma unroll
                    for (int rh = 0; rh < 2; ++rh) {
                        int r = wm * 32 + mt * 16 + rh * 8 + gID;
                        const float* rs = reds + r * 4;
                        float st = (rs[0] + rs[1]) + (rs[2] + rs[3]);
                        L[mt][rh] = M[mt][rh] + logf(st);
                    }

                #pragma unroll
                for (int mt = 0; mt < 2; ++mt)
                    #pragma unroll
                    for (int rh = 0; rh < 2; ++rh) {
                        int r = wm * 32 + mt * 16 + rh * 8 + gID;
                        float lse = L[mt][rh];
                        #pragma unroll
                        for (int nt = 0; nt < 8; ++nt) {
                            int n0 = nBase + nt * 8 + lq * 2;
                            float2 o;
                            o.x = acc[mt][nt][rh*2]   - lse;
                            o.y = acc[mt][nt][rh*2+1] - lse;
                            *(float2*)(outLS + (size_t)(rbase + r) * 256 + n0) = o;
                        }
                    }
            }
        }
    }
}

extern "C" void kernel_launch(void* const* d_in, const int* in_sizes, int n_in,
                              void* d_out, int out_size)
{
    (void)in_sizes; (void)n_in; (void)out_size;
    const float* input  = (const float*)d_in[0];
    const float* hidden = (const float*)d_in[1];
    const float* w_i2h  = (const float*)d_in[2];
    const float* b_i2h  = (const float*)d_in[3];
    const float* w_i2o  = (const float*)d_in[4];
    const float* b_i2o  = (const float*)d_in[5];
    float* out = (float*)d_out;

    repack_kernel<<<(NTILES * TILE_U32 + 255) / 256, 256>>>(w_i2h, w_i2o);

    cudaFuncSetAttribute(lstm_mma_kernel,
                         cudaFuncAttributeMaxDynamicSharedMemorySize,
                         SMEM_TOTAL);
    lstm_mma_kernel<<<BATCH / MT, THREADS, SMEM_TOTAL>>>(
        input, hidden, b_i2h, b_i2o, out);
}

// round 15
// speedup vs baseline: 1.4742x; 1.4698x over previous
#include <cuda_runtime.h>
#include <cuda_fp16.h>
#include <cstdint>
#include <math.h>

// LSTM_2370821948014 — round 14: R13 skeleton + MUFU activations + ALU diet.
// tanh via tanh.approx.f32 (1 MUFU); sigmoid via 0.5*tanh(x/2)+0.5.
// Loop bookkeeping (kt/chunk/phase) kept as running counters.
// MT=64 rows/CTA (1024 CTAs), 256 thr (8 warps, 2M x 4N, warp tile 32x64),
// 60 W tiles of 128 rows x 64 k fp16 (16KB), NBUF=3, 2 CTAs/SM.

static constexpr int BATCH = 65536;
static constexpr int ODIM  = 256;
static constexpr int KDIM  = 384;
static constexpr int MT    = 64;
static constexpr int THREADS = 256;
static constexpr int NBUF = 3;
static constexpr int NTILES  = 60;        // 5 chunks x 6 kt x 2 halves
static constexpr int TILE_U32 = 4096;     // 128 rows x 32 words (16KB)

// SMEM layout (bytes), per CTA
static constexpr int PA2     = 196;                 // A pitch (u32, fp16 pairs)
static constexpr int SM_A    = 0;                   // 64*196*4 = 50176
static constexpr int SM_W    = 50176;               // 3 x 16384 = 49152
static constexpr int WB      = 16384;
static constexpr int SM_REDM = SM_W + NBUF * WB;    // 99328 (256 floats)
static constexpr int SM_REDS = SM_REDM + 1024;      // 100352
static constexpr int SM_MB   = SM_REDS + 1024;      // 101376: full[3] cons[3]
static constexpr int SMEM_TOTAL = SM_MB + 64;       // 101440

__device__ uint32_t w_packed[NTILES * TILE_U32];    // ~0.98MB scratch

// ---------------- helpers ----------------

__device__ __forceinline__ uint32_t smem_u32(const void* p) {
    uint32_t a;
    asm("{ .reg .u64 t; cvta.to.shared.u64 t, %1; cvt.u32.u64 %0, t; }"
        : "=r"(a) : "l"(p));
    return a;
}

__device__ __forceinline__ uint32_t pack_h2(float x, float y) {
    __half2 h = __floats2half2_rn(x, y);
    return *reinterpret_cast<uint32_t*>(&h);
}

__device__ __forceinline__ void mbar_init(uint32_t a, uint32_t cnt) {
    asm volatile("mbarrier.init.shared.b64 [%0], %1;" :: "r"(a), "r"(cnt) : "memory");
}

__device__ __forceinline__ void mbar_expect_tx(uint32_t a, uint32_t bytes) {
    asm volatile("mbarrier.arrive.expect_tx.shared.b64 _, [%0], %1;"
                 :: "r"(a), "r"(bytes) : "memory");
}

__device__ __forceinline__ void mbar_arrive(uint32_t a) {
    asm volatile("mbarrier.arrive.shared.b64 _, [%0];" :: "r"(a) : "memory");
}

__device__ __forceinline__ void mbar_wait(uint32_t a, uint32_t parity) {
    asm volatile(
        "{\n\t"
        ".reg .pred P;\n\t"
        "W%=:\n\t"
        "mbarrier.try_wait.parity.acquire.cta.shared::cta.b64 P, [%0], %1, 0x989680;\n\t"
        "@P bra D%=;\n\t"
        "bra W%=;\n\t"
        "D%=:\n\t"
        "}"
        :: "r"(a), "r"(parity) : "memory");
}

__device__ __forceinline__ void bulk_ld(uint32_t dst, const void* src,
                                        uint32_t bytes, uint32_t mbar) {
    asm volatile(
        "cp.async.bulk.shared::cluster.global.mbarrier::complete_tx::bytes "
        "[%0], [%1], %2, [%3];"
        :: "r"(dst), "l"(src), "r"(bytes), "r"(mbar) : "memory");
}

__device__ __forceinline__ void ldsm4(uint32_t* r, uint32_t addr) {
    asm volatile(
        "ldmatrix.sync.aligned.m8n8.x4.shared.b16 {%0,%1,%2,%3}, [%4];"
        : "=r"(r[0]), "=r"(r[1]), "=r"(r[2]), "=r"(r[3]) : "r"(addr));
}

__device__ __forceinline__ void mma16(float* d, const uint32_t* a,
                                      uint32_t b0, uint32_t b1) {
    asm volatile(
        "mma.sync.aligned.m16n8k16.row.col.f32.f16.f16.f32 "
        "{%0,%1,%2,%3}, {%4,%5,%6,%7}, {%8,%9}, {%0,%1,%2,%3};"
        : "+f"(d[0]), "+f"(d[1]), "+f"(d[2]), "+f"(d[3])
        : "r"(a[0]), "r"(a[1]), "r"(a[2]), "r"(a[3]), "r"(b0), "r"(b1));
}

__device__ __forceinline__ float tanh_hw(float x) {
    float y;
    asm("tanh.approx.f32 %0, %1;" : "=f"(y) : "f"(x));
    return y;
}
__device__ __forceinline__ float sigf(float x) {
    return fmaf(tanh_hw(0.5f * x), 0.5f, 0.5f);
}

// ---------------- repack kernel ----------------
// tile t = chunk*12 + kt*2 + half  (kt: 64-k window; half: N-half).
// Gates chunks (0..3): tile row v (0..127): wn = half*2 + (v>>6),
//   nt=(v>>3)&7, jlo=v&7, g=nt>>1, jh=nt&1 ->
//   w_i2h row g*256 + chunk*64 + wn*16 + jh*8 + jlo.
// Logits chunk (4): row = half*128 + v.
// Row v holds 32 fp16-pair words (k = kt*64 + 2w); stored u32 index
//   v*32 + (((w>>2) ^ (v&7)) << 2) + (w&3).

__global__ void repack_kernel(const float* __restrict__ w_i2h,
                              const float* __restrict__ w_i2o)
{
    int i = blockIdx.x * 256 + threadIdx.x;
    if (i >= NTILES * TILE_U32) return;
    int t  = i / TILE_U32;
    int e  = i - t * TILE_U32;
    int v  = e >> 5;
    int w  = e & 31;
    int chunk = t / 12;
    int r12   = t - chunk * 12;
    int kt    = r12 >> 1;
    int half  = r12 & 1;
    const float* src;
    int row;
    if (chunk < 4) {
        int wn  = half * 2 + (v >> 6);
        int nt  = (v >> 3) & 7;
        int jlo = v & 7;
        int g   = nt >> 1;
        int jh  = nt & 1;
        row = g * 256 + chunk * 64 + wn * 16 + jh * 8 + jlo;
        src = w_i2h;
    } else {
        row = half * 128 + v;
        src = w_i2o;
    }
    const float* p = src + (size_t)row * KDIM + kt * 64 + w * 2;
    w_packed[t * TILE_U32 + v * 32 + (((w >> 2) ^ (v & 7)) << 2) + (w & 3)] =
        pack_h2(p[0], p[1]);
}

// ---------------- main kernel ----------------

__global__ __launch_bounds__(THREADS, 2)
void lstm_mma_kernel(const float* __restrict__ input,
                     const float* __restrict__ hidden,
                     const float* __restrict__ b_i2h,
                     const float* __restrict__ b_i2o,
                     float* __restrict__ out)
{
    extern __shared__ char smem[];
    const uint32_t sbase = smem_u32(smem);
    const int tid  = threadIdx.x;
    const int wid  = tid >> 5;
    const int lane = tid & 31;
    const int wm   = wid >> 2;          // 0..1 (M)
    const int wn   = wid & 3;           // 0..3 (N)
    const int gID  = lane >> 2;         // 0..7
    const int lq   = lane & 3;          // 0..3
    const int myHalf = wn >> 1;
    const int rbase = blockIdx.x * MT;
    const bool isProd = (tid == 0);

    uint32_t* Au2 = (uint32_t*)(smem + SM_A);
    const uint32_t fullB = sbase + SM_MB;        // 3 x 8B
    const uint32_t consB = sbase + SM_MB + 24;   // 3 x 8B

    // ldmatrix A addresses
    const int aRow  = wm * 32 + (lane & 7) + 8 * ((lane >> 3) & 1);
    const int aKsel = 4 * ((lane >> 4) & 1);
    const uint32_t aBase0 = sbase + SM_A + (uint32_t)(aRow * PA2 + aKsel) * 4;
    const uint32_t aBase1 = aBase0 + 16 * PA2 * 4;

    // ldmatrix B addresses
    const int bKb      = (lane >> 3) & 1;
    const int bRowBase = (wn & 1) * 64 + 8 * ((lane >> 4) & 1) + (lane & 7);
    const int bMask    = bRowBase & 7;
    const uint32_t bOff0 = (uint32_t)bRowBase * 128;
    const uint32_t bOff1 = bOff0 + 16 * 128;
    const uint32_t bOff2 = bOff0 + 32 * 128;
    const uint32_t bOff3 = bOff0 + 48 * 128;

    if (tid == 0) {
        for (int b = 0; b < NBUF; ++b) {
            mbar_init(fullB + 8 * b, 1);
            mbar_init(consB + 8 * b, 8);
        }
    }
    __syncthreads();

    if (isProd) {
        for (int u = 0; u < NBUF; ++u) {
            mbar_expect_tx(fullB + 8 * u, WB);
            bulk_ld(sbase + SM_W + u * WB, w_packed + (size_t)u * TILE_U32,
                    WB, fullB + 8 * u);
        }
    }

    // stage A (fp16 pairs, pitch 196 u32)
    for (int idx = tid; idx < MT * 96; idx += THREADS) {
        int r  = idx / 96;
        int c4 = idx - r * 96;
        float4 v = (c4 < 32)
            ? *(const float4*)(input  + (size_t)(rbase + r) * 128 + c4 * 4)
            : *(const float4*)(hidden + (size_t)(rbase + r) * 256 + (c4 - 32) * 4);
        uint2 u;
        u.x = pack_h2(v.x, v.y);
        u.y = pack_h2(v.z, v.w);
        *(uint2*)(Au2 + r * PA2 + c4 * 2) = u;
    }
    __syncthreads();

    float* outLS = out;
    float* outNH = out + (size_t)BATCH * ODIM;

    float acc[2][8][4];
    #pragma unroll
    for (int m = 0; m < 2; ++m)
        #pragma unroll
        for (int n = 0; n < 8; ++n)
            #pragma unroll
            for (int c = 0; c < 4; ++c) acc[m][n][c] = 0.0f;

    // running counters (no div/mod in hot loop)
    int buf = 0, fullPh = 0, r12 = 0, chunk = 0;
    int phCnt = 0;   // tiles consumed in current phase cycle

    for (int t = 0; t < NTILES; ++t) {
        mbar_wait(fullB + 8 * buf, fullPh);

        if ((r12 & 1) == myHalf) {
            const uint32_t Wbase = sbase + SM_W + buf * WB;
            const uint32_t aK = (uint32_t)((r12 >> 1) * 128);

            #pragma unroll
            for (int ks = 0; ks < 4; ++ks) {
                uint32_t a0[4], a1[4], b[16];
                const uint32_t aoff = aK + ks * 32;
                ldsm4(a0, aBase0 + aoff);
                ldsm4(a1, aBase1 + aoff);
                const uint32_t c = (uint32_t)(((2 * ks + bKb) ^ bMask) << 4);
                ldsm4(b + 0,  Wbase + bOff0 + c);
                ldsm4(b + 4,  Wbase + bOff1 + c);
                ldsm4(b + 8,  Wbase + bOff2 + c);
                ldsm4(b + 12, Wbase + bOff3 + c);
                #pragma unroll
                for (int p = 0; p < 4; ++p) {
                    mma16(acc[0][2*p],   a0, b[4*p],   b[4*p+1]);
                    mma16(acc[1][2*p],   a1, b[4*p],   b[4*p+1]);
                    mma16(acc[0][2*p+1], a0, b[4*p+2], b[4*p+3]);
                    mma16(acc[1][2*p+1], a1, b[4*p+2], b[4*p+3]);
                }
            }
        }

        if (lane == 0) mbar_arrive(consB + 8 * buf);

        if (isProd && t + NBUF < NTILES) {
            mbar_wait(consB + 8 * buf, fullPh);
            mbar_expect_tx(fullB + 8 * buf, WB);
            bulk_ld(sbase + SM_W + buf * WB,
                    w_packed + (size_t)(t + NBUF) * TILE_U32, WB,
                    fullB + 8 * buf);
        }

        if (r12 == 11) {
            if (chunk < 4) {
                // ---- LSTM epilogue (MUFU activations) ----
                #pragma unroll
                for (int mt = 0; mt < 2; ++mt)
                    #pragma unroll
                    for (int rh = 0; rh < 2; ++rh)
                        #pragma unroll
                        for (int jh = 0; jh < 2; ++jh) {
                            int r  = wm * 32 + mt * 16 + rh * 8 + gID;
                            int j0 = chunk * 64 + wn * 16 + jh * 8 + lq * 2;
                            int ci = rh * 2;
                            float h0 = acc[mt][jh][ci]     + b_i2h[j0];
                            float h1 = acc[mt][jh][ci+1]   + b_i2h[j0+1];
                            float i0 = acc[mt][2+jh][ci]   + b_i2h[256+j0];
                            float i1 = acc[mt][2+jh][ci+1] + b_i2h[256+j0+1];
                            float f0 = acc[mt][4+jh][ci]   + b_i2h[512+j0];
                            float f1 = acc[mt][4+jh][ci+1] + b_i2h[512+j0+1];
                            float o0 = acc[mt][6+jh][ci]   + b_i2h[768+j0];
                            float o1 = acc[mt][6+jh][ci+1] + b_i2h[768+j0+1];
                            float2 hv = *(const float2*)(
                                hidden + (size_t)(rbase + r) * 256 + j0);
                            float2 nh;
                            nh.x = sigf(o0) * tanh_hw(sigf(f0) * hv.x + sigf(i0) * tanh_hw(h0));
                            nh.y = sigf(o1) * tanh_hw(sigf(f1) * hv.y + sigf(i1) * tanh_hw(h1));
                            *(float2*)(outNH + (size_t)(rbase + r) * 256 + j0) = nh;
                        }
                #pragma unroll
                for (int m = 0; m < 2; ++m)
                    #pragma unroll
                    for (int n = 0; n < 8; ++n)
                        #pragma unroll
                        for (int c = 0; c < 4; ++c) acc[m][n][c] = 0.0f;
            } else {
                // ---- logits epilogue: log_softmax over 256 cols ----
                const int nBase = myHalf * 128 + (wn & 1) * 64;
                float* redm = (float*)(smem + SM_REDM);
                float* reds = (float*)(smem + SM_REDS);

                #pragma unroll
                for (int mt = 0; mt < 2; ++mt)
                    #pragma unroll
                    for (int nt = 0; nt < 8; ++nt) {
                        int n0 = nBase + nt * 8 + lq * 2;
                        float bz0 = b_i2o[n0], bz1 = b_i2o[n0 + 1];
                        acc[mt][nt][0] += bz0;
                        acc[mt][nt][1] += bz1;
                        acc[mt][nt][2] += bz0;
                        acc[mt][nt][3] += bz1;
                    }

                #pragma unroll
                for (int mt = 0; mt < 2; ++mt)
                    #pragma unroll
                    for (int rh = 0; rh < 2; ++rh) {
                        float m = -3.4e38f;
                        #pragma unroll
                        for (int nt = 0; nt < 8; ++nt) {
                            m = fmaxf(m, acc[mt][nt][rh*2]);
                            m = fmaxf(m, acc[mt][nt][rh*2+1]);
                        }
                        m = fmaxf(m, __shfl_xor_sync(0xffffffffu, m, 1));
                        m = fmaxf(m, __shfl_xor_sync(0xffffffffu, m, 2));
                        if (lq == 0) {
                            int r = wm * 32 + mt * 16 + rh * 8 + gID;
                            redm[r * 4 + wn] = m;
                        }
                    }
                __syncthreads();

                float M[2][2], L[2][2];
                #pragma unroll
                for (int mt = 0; mt < 2; ++mt)
                    #pragma unroll
                    for (int rh = 0; rh < 2; ++rh) {
                        int r = wm * 32 + mt * 16 + rh * 8 + gID;
                        const float* rm = redm + r * 4;
                        float m = fmaxf(fmaxf(rm[0], rm[1]),
                                        fmaxf(rm[2], rm[3]));
                        M[mt][rh] = m;
                        float s = 0.0f;
                        #pragma unroll
                        for (int nt = 0; nt < 8; ++nt) {
                            s += __expf(acc[mt][nt][rh*2]   - m);
                            s += __expf(acc[mt][nt][rh*2+1] - m);
                        }
                        s += __shfl_xor_sync(0xffffffffu, s, 1);
                        s += __shfl_xor_sync(0xffffffffu, s, 2);
                        if (lq == 0) reds[r * 4 + wn] = s;
                    }
                __syncthreads();

                #pragma unroll
                for (int mt = 0; mt < 2; ++mt)
                    #pragma unroll
                    for (int rh = 0; rh < 2; ++rh) {
                        int r = wm * 32 + mt * 16 + rh * 8 + gID;
                        const float* rs = reds + r * 4;
                        float st = (rs[0] + rs[1]) + (rs[2] + rs[3]);
                        L[mt][rh] = M[mt][rh] + __logf(st);
                    }

                #pragma unroll
                for (int mt = 0; mt < 2; ++mt)
                    #pragma unroll
                    for (int rh = 0; rh < 2; ++rh) {
                        int r = wm * 32 + mt * 16 + rh * 8 + gID;
                        float lse = L[mt][rh];
                        #pragma unroll
                        for (int nt = 0; nt < 8; ++nt) {
                            int n0 = nBase + nt * 8 + lq * 2;
                            float2 o;
                            o.x = acc[mt][nt][rh*2]   - lse;
                            o.y = acc[mt][nt][rh*2+1] - lse;
                            *(float2*)(outLS + (size_t)(rbase + r) * 256 + n0) = o;
                        }
                    }
            }
            r12 = 0;
            ++chunk;
        } else {
            ++r12;
        }
        // advance ring counters
        if (++buf == NBUF) buf = 0;
        if (++phCnt == NBUF) { phCnt = 0; fullPh ^= 1; }
    }
}

extern "C" void kernel_launch(void* const* d_in, const int* in_sizes, int n_in,
                              void* d_out, int out_size)
{
    (void)in_sizes; (void)n_in; (void)out_size;
    const float* input  = (const float*)d_in[0];
    const float* hidden = (const float*)d_in[1];
    const float* w_i2h  = (const float*)d_in[2];
    const float* b_i2h  = (const float*)d_in[3];
    const float* w_i2o  = (const float*)d_in[4];
    const float* b_i2o  = (const float*)d_in[5];
    float* out = (float*)d_out;

    repack_kernel<<<(NTILES * TILE_U32 + 255) / 256, 256>>>(w_i2h, w_i2o);

    cudaFuncSetAttribute(lstm_mma_kernel,
                         cudaFuncAttributeMaxDynamicSharedMemorySize,
                         SMEM_TOTAL);
    lstm_mma_kernel<<<BATCH / MT, THREADS, SMEM_TOTAL>>>(
        input, hidden, b_i2h, b_i2o, out);
}

// round 16
// speedup vs baseline: 1.6409x; 1.1130x over previous
#include <cuda_runtime.h>
#include <cuda_fp16.h>
#include <cstdint>
#include <math.h>

// LSTM_2370821948014 — round 15: paired 32KB tiles (30), every warp computes
// every buffer -> half the barrier ops of R14. NBUF=2. A pitch 192 u32 with
// XOR chunk swizzle (no pad); softmax reduce arrays alias the dead A region.
// MT=64 rows/CTA (1024 CTAs), 256 thr (8 warps, 2M x 4N, warp tile 32x64),
// mma.sync.m16n8k16.f16 + ldmatrix, MUFU activations, 2 CTAs/SM.

static constexpr int BATCH = 65536;
static constexpr int ODIM  = 256;
static constexpr int KDIM  = 384;
static constexpr int MT    = 64;
static constexpr int THREADS = 256;
static constexpr int NPAIR = 30;          // 5 chunks x 6 kt
static constexpr int PAIR_U32 = 8192;     // 256 rows x 32 words (32KB)

// SMEM layout (bytes), per CTA
static constexpr int SM_A    = 0;                   // 64 rows * 768B = 49152
static constexpr int SM_W    = 49152;               // 2 x 32768 = 65536
static constexpr int WB      = 32768;
static constexpr int SM_MB   = 114688;              // full[2] cons[2] = 32B
static constexpr int SMEM_TOTAL = 114720;
// reduce arrays alias dead A region (used only in final logits epilogue)
static constexpr int SM_REDM = 0;
static constexpr int SM_REDS = 1024;

__device__ uint32_t w_packed[NPAIR * PAIR_U32];     // ~0.98MB scratch

// ---------------- helpers ----------------

__device__ __forceinline__ uint32_t smem_u32(const void* p) {
    uint32_t a;
    asm("{ .reg .u64 t; cvta.to.shared.u64 t, %1; cvt.u32.u64 %0, t; }"
        : "=r"(a) : "l"(p));
    return a;
}

__device__ __forceinline__ uint32_t pack_h2(float x, float y) {
    __half2 h = __floats2half2_rn(x, y);
    return *reinterpret_cast<uint32_t*>(&h);
}

__device__ __forceinline__ void mbar_init(uint32_t a, uint32_t cnt) {
    asm volatile("mbarrier.init.shared.b64 [%0], %1;" :: "r"(a), "r"(cnt) : "memory");
}

__device__ __forceinline__ void mbar_expect_tx(uint32_t a, uint32_t bytes) {
    asm volatile("mbarrier.arrive.expect_tx.shared.b64 _, [%0], %1;"
                 :: "r"(a), "r"(bytes) : "memory");
}

__device__ __forceinline__ void mbar_arrive(uint32_t a) {
    asm volatile("mbarrier.arrive.shared.b64 _, [%0];" :: "r"(a) : "memory");
}

__device__ __forceinline__ void mbar_wait(uint32_t a, uint32_t parity) {
    asm volatile(
        "{\n\t"
        ".reg .pred P;\n\t"
        "W%=:\n\t"
        "mbarrier.try_wait.parity.acquire.cta.shared::cta.b64 P, [%0], %1, 0x989680;\n\t"
        "@P bra D%=;\n\t"
        "bra W%=;\n\t"
        "D%=:\n\t"
        "}"
        :: "r"(a), "r"(parity) : "memory");
}

__device__ __forceinline__ void bulk_ld(uint32_t dst, const void* src,
                                        uint32_t bytes, uint32_t mbar) {
    asm volatile(
        "cp.async.bulk.shared::cluster.global.mbarrier::complete_tx::bytes "
        "[%0], [%1], %2, [%3];"
        :: "r"(dst), "l"(src), "r"(bytes), "r"(mbar) : "memory");
}

__device__ __forceinline__ void ldsm4(uint32_t* r, uint32_t addr) {
    asm volatile(
        "ldmatrix.sync.aligned.m8n8.x4.shared.b16 {%0,%1,%2,%3}, [%4];"
        : "=r"(r[0]), "=r"(r[1]), "=r"(r[2]), "=r"(r[3]) : "r"(addr));
}

__device__ __forceinline__ void mma16(float* d, const uint32_t* a,
                                      uint32_t b0, uint32_t b1) {
    asm volatile(
        "mma.sync.aligned.m16n8k16.row.col.f32.f16.f16.f32 "
        "{%0,%1,%2,%3}, {%4,%5,%6,%7}, {%8,%9}, {%0,%1,%2,%3};"
        : "+f"(d[0]), "+f"(d[1]), "+f"(d[2]), "+f"(d[3])
        : "r"(a[0]), "r"(a[1]), "r"(a[2]), "r"(a[3]), "r"(b0), "r"(b1));
}

__device__ __forceinline__ float tanh_hw(float x) {
    float y;
    asm("tanh.approx.f32 %0, %1;" : "=f"(y) : "f"(x));
    return y;
}
__device__ __forceinline__ float sigf(float x) {
    return fmaf(tanh_hw(0.5f * x), 0.5f, 0.5f);
}

// ---------------- repack kernel ----------------
// pair P = chunk*6 + kt (kt: 64-k window). Super-row v2 (0..255):
//   half = v2>>7, v = v2&127.
// Gates chunks (0..3): wn = half*2 + (v>>6), nt=(v>>3)&7, jlo=v&7,
//   g=nt>>1, jh=nt&1 -> w_i2h row g*256 + chunk*64 + wn*16 + jh*8 + jlo.
// Logits chunk (4): row = half*128 + v.
// Row v2 holds 32 fp16-pair words (k = kt*64 + 2w); stored u32 index
//   v2*32 + (((w>>2) ^ (v2&7)) << 2) + (w&3).

__global__ void repack_kernel(const float* __restrict__ w_i2h,
                              const float* __restrict__ w_i2o)
{
    int i = blockIdx.x * 256 + threadIdx.x;
    if (i >= NPAIR * PAIR_U32) return;
    int P  = i >> 13;
    int e  = i & 8191;
    int v2 = e >> 5;
    int w  = e & 31;
    int chunk = P / 6;
    int kt    = P - chunk * 6;
    int half  = v2 >> 7;
    int v     = v2 & 127;
    const float* src;
    int row;
    if (chunk < 4) {
        int wn  = half * 2 + (v >> 6);
        int nt  = (v >> 3) & 7;
        int jlo = v & 7;
        int g   = nt >> 1;
        int jh  = nt & 1;
        row = g * 256 + chunk * 64 + wn * 16 + jh * 8 + jlo;
        src = w_i2h;
    } else {
        row = half * 128 + v;
        src = w_i2o;
    }
    const float* p = src + (size_t)row * KDIM + kt * 64 + w * 2;
    w_packed[P * PAIR_U32 + v2 * 32 + (((w >> 2) ^ (v2 & 7)) << 2) + (w & 3)] =
        pack_h2(p[0], p[1]);
}

// ---------------- main kernel ----------------

__global__ __launch_bounds__(THREADS, 2)
void lstm_mma_kernel(const float* __restrict__ input,
                     const float* __restrict__ hidden,
                     const float* __restrict__ b_i2h,
                     const float* __restrict__ b_i2o,
                     float* __restrict__ out)
{
    extern __shared__ char smem[];
    const uint32_t sbase = smem_u32(smem);
    const int tid  = threadIdx.x;
    const int wid  = tid >> 5;
    const int lane = tid & 31;
    const int wm   = wid >> 2;          // 0..1 (M)
    const int wn   = wid & 3;           // 0..3 (N)
    const int gID  = lane >> 2;         // 0..7
    const int lq   = lane & 3;          // 0..3
    const int myHalf = wn >> 1;
    const int rbase = blockIdx.x * MT;
    const bool isProd = (tid == 0);

    uint32_t* Au2 = (uint32_t*)(smem + SM_A);
    const uint32_t fullB = sbase + SM_MB;        // 2 x 8B
    const uint32_t consB = sbase + SM_MB + 16;   // 2 x 8B

    // ldmatrix A addressing (pitch 192 u32 = 768B, chunk-XOR swizzle):
    // lane row = aRow (+16 for second ldsm); lane 16B-chunk = kt*8+ks*2+khalf,
    // swizzled by ^(row&7).
    const int aRow  = wm * 32 + (lane & 7) + 8 * ((lane >> 3) & 1);
    const int khalf = (lane >> 4) & 1;
    const int amask = aRow & 7;                  // (aRow+16)&7 == amask
    const uint32_t aRowB0 = sbase + SM_A + (uint32_t)aRow * 768;
    const uint32_t aRowB1 = aRowB0 + 16 * 768;

    // ldmatrix B addressing (within this warp's 16KB half of the pair)
    const int bKb      = (lane >> 3) & 1;
    const int bRowBase = (wn & 1) * 64 + 8 * ((lane >> 4) & 1) + (lane & 7);
    const int bMask    = bRowBase & 7;
    const uint32_t bOff0 = (uint32_t)bRowBase * 128;
    const uint32_t bOff1 = bOff0 + 16 * 128;
    const uint32_t bOff2 = bOff0 + 32 * 128;
    const uint32_t bOff3 = bOff0 + 48 * 128;
    const uint32_t bHalfOff = (uint32_t)myHalf * 16384;

    if (tid == 0) {
        for (int b = 0; b < 2; ++b) {
            mbar_init(fullB + 8 * b, 1);
            mbar_init(consB + 8 * b, 8);
        }
    }
    __syncthreads();

    // prologue: load pairs 0,1 (overlaps A staging)
    if (isProd) {
        for (int u = 0; u < 2; ++u) {
            mbar_expect_tx(fullB + 8 * u, WB);
            bulk_ld(sbase + SM_W + u * WB, w_packed + (size_t)u * PAIR_U32,
                    WB, fullB + 8 * u);
        }
    }

    // stage A: fp16 pairs, pitch 192 u32, chunk c (16B) stored at c^(r&7)
    for (int idx = tid; idx < MT * 96; idx += THREADS) {
        int r  = idx / 96;
        int c4 = idx - r * 96;
        float4 v = (c4 < 32)
            ? *(const float4*)(input  + (size_t)(rbase + r) * 128 + c4 * 4)
            : *(const float4*)(hidden + (size_t)(rbase + r) * 256 + (c4 - 32) * 4);
        uint2 u;
        u.x = pack_h2(v.x, v.y);
        u.y = pack_h2(v.z, v.w);
        int c2 = c4 >> 1;
        uint32_t off = (uint32_t)(r * 192 + (((c2) ^ (r & 7)) << 2) + (c4 & 1) * 2);
        *(uint2*)(Au2 + off) = u;
    }
    __syncthreads();

    float* outLS = out;
    float* outNH = out + (size_t)BATCH * ODIM;

    float acc[2][8][4];
    #pragma unroll
    for (int m = 0; m < 2; ++m)
        #pragma unroll
        for (int n = 0; n < 8; ++n)
            #pragma unroll
            for (int c = 0; c < 4; ++c) acc[m][n][c] = 0.0f;

    int buf = 0, ph = 0, kt = 0, chunk = 0;

    for (int P = 0; P < NPAIR; ++P) {
        mbar_wait(fullB + 8 * buf, ph);

        const uint32_t Wbase = sbase + SM_W + buf * WB + bHalfOff;
        const int cb = kt * 8 + khalf;   // A chunk base for this thread

        #pragma unroll
        for (int ks = 0; ks < 4; ++ks) {
            uint32_t a0[4], a1[4], b[16];
            const uint32_t coff = (uint32_t)(((cb + ks * 2) ^ amask) << 4);
            ldsm4(a0, aRowB0 + coff);
            ldsm4(a1, aRowB1 + coff);
            const uint32_t c = (uint32_t)(((2 * ks + bKb) ^ bMask) << 4);
            ldsm4(b + 0,  Wbase + bOff0 + c);
            ldsm4(b + 4,  Wbase + bOff1 + c);
            ldsm4(b + 8,  Wbase + bOff2 + c);
            ldsm4(b + 12, Wbase + bOff3 + c);
            #pragma unroll
            for (int p = 0; p < 4; ++p) {
                mma16(acc[0][2*p],   a0, b[4*p],   b[4*p+1]);
                mma16(acc[1][2*p],   a1, b[4*p],   b[4*p+1]);
                mma16(acc[0][2*p+1], a0, b[4*p+2], b[4*p+3]);
                mma16(acc[1][2*p+1], a1, b[4*p+2], b[4*p+3]);
            }
        }

        if (lane == 0) mbar_arrive(consB + 8 * buf);

        if (isProd && P + 2 < NPAIR) {
            mbar_wait(consB + 8 * buf, ph);
            mbar_expect_tx(fullB + 8 * buf, WB);
            bulk_ld(sbase + SM_W + buf * WB,
                    w_packed + (size_t)(P + 2) * PAIR_U32, WB,
                    fullB + 8 * buf);
        }

        if (kt == 5) {
            if (chunk < 4) {
                // ---- LSTM epilogue (MUFU activations) ----
                #pragma unroll
                for (int mt = 0; mt < 2; ++mt)
                    #pragma unroll
                    for (int rh = 0; rh < 2; ++rh)
                        #pragma unroll
                        for (int jh = 0; jh < 2; ++jh) {
                            int r  = wm * 32 + mt * 16 + rh * 8 + gID;
                            int j0 = chunk * 64 + wn * 16 + jh * 8 + lq * 2;
                            int ci = rh * 2;
                            float h0 = acc[mt][jh][ci]     + b_i2h[j0];
                            float h1 = acc[mt][jh][ci+1]   + b_i2h[j0+1];
                            float i0 = acc[mt][2+jh][ci]   + b_i2h[256+j0];
                            float i1 = acc[mt][2+jh][ci+1] + b_i2h[256+j0+1];
                            float f0 = acc[mt][4+jh][ci]   + b_i2h[512+j0];
                            float f1 = acc[mt][4+jh][ci+1] + b_i2h[512+j0+1];
                            float o0 = acc[mt][6+jh][ci]   + b_i2h[768+j0];
                            float o1 = acc[mt][6+jh][ci+1] + b_i2h[768+j0+1];
                            float2 hv = *(const float2*)(
                                hidden + (size_t)(rbase + r) * 256 + j0);
                            float2 nh;
                            nh.x = sigf(o0) * tanh_hw(sigf(f0) * hv.x + sigf(i0) * tanh_hw(h0));
                            nh.y = sigf(o1) * tanh_hw(sigf(f1) * hv.y + sigf(i1) * tanh_hw(h1));
                            *(float2*)(outNH + (size_t)(rbase + r) * 256 + j0) = nh;
                        }
                #pragma unroll
                for (int m = 0; m < 2; ++m)
                    #pragma unroll
                    for (int n = 0; n < 8; ++n)
                        #pragma unroll
                        for (int c = 0; c < 4; ++c) acc[m][n][c] = 0.0f;
            } else {
                // ---- logits epilogue: log_softmax over 256 cols ----
                // reduce arrays alias the (now dead) A region.
                __syncthreads();
                const int nBase = myHalf * 128 + (wn & 1) * 64;
                float* redm = (float*)(smem + SM_REDM);
                float* reds = (float*)(smem + SM_REDS);

                #pragma unroll
                for (int mt = 0; mt < 2; ++mt)
                    #pragma unroll
                    for (int nt = 0; nt < 8; ++nt) {
                        int n0 = nBase + nt * 8 + lq * 2;
                        float bz0 = b_i2o[n0], bz1 = b_i2o[n0 + 1];
                        acc[mt][nt][0] += bz0;
                        acc[mt][nt][1] += bz1;
                        acc[mt][nt][2] += bz0;
                        acc[mt][nt][3] += bz1;
                    }

                #pragma unroll
                for (int mt = 0; mt < 2; ++mt)
                    #pragma unroll
                    for (int rh = 0; rh < 2; ++rh) {
                        float m = -3.4e38f;
                        #pragma unroll
                        for (int nt = 0; nt < 8; ++nt) {
                            m = fmaxf(m, acc[mt][nt][rh*2]);
                            m = fmaxf(m, acc[mt][nt][rh*2+1]);
                        }
                        m = fmaxf(m, __shfl_xor_sync(0xffffffffu, m, 1));
                        m = fmaxf(m, __shfl_xor_sync(0xffffffffu, m, 2));
                        if (lq == 0) {
                            int r = wm * 32 + mt * 16 + rh * 8 + gID;
                            redm[r * 4 + wn] = m;
                        }
                    }
                __syncthreads();

                float M[2][2], L[2][2];
                #pragma unroll
                for (int mt = 0; mt < 2; ++mt)
                    #pragma unroll
                    for (int rh = 0; rh < 2; ++rh) {
                        int r = wm * 32 + mt * 16 + rh * 8 + gID;
                        const float* rm = redm + r * 4;
                        float m = fmaxf(fmaxf(rm[0], rm[1]),
                                        fmaxf(rm[2], rm[3]));
                        M[mt][rh] = m;
                        float s = 0.0f;
                        #pragma unroll
                        for (int nt = 0; nt < 8; ++nt) {
                            s += __expf(acc[mt][nt][rh*2]   - m);
                            s += __expf(acc[mt][nt][rh*2+1] - m);
                        }
                        s += __shfl_xor_sync(0xffffffffu, s, 1);
                        s += __shfl_xor_sync(0xffffffffu, s, 2);
                        if (lq == 0) reds[r * 4 + wn] = s;
                    }
                __syncthreads();

                #pragma unroll
                for (int mt = 0; mt < 2; ++mt)
                    #pragma unroll
                    for (int rh = 0; rh < 2; ++rh) {
                        int r = wm * 32 + mt * 16 + rh * 8 + gID;
                        const float* rs = reds + r * 4;
                        float st = (rs[0] + rs[1]) + (rs[2] + rs[3]);
                        L[mt][rh] = M[mt][rh] + __logf(st);
                    }

                #pragma unroll
                for (int mt = 0; mt < 2; ++mt)
                    #pragma unroll
                    for (int rh = 0; rh < 2; ++rh) {
                        int r = wm * 32 + mt * 16 + rh * 8 + gID;
                        float lse = L[mt][rh];
                        #pragma unroll
                        for (int nt = 0; nt < 8; ++nt) {
                            int n0 = nBase + nt * 8 + lq * 2;
                            float2 o;
                            o.x = acc[mt][nt][rh*2]   - lse;
                            o.y = acc[mt][nt][rh*2+1] - lse;
                            *(float2*)(outLS + (size_t)(rbase + r) * 256 + n0) = o;
                        }
                    }
            }
            kt = 0;
            ++chunk;
        } else {
            ++kt;
        }
        buf ^= 1;
        if (buf == 0) ph ^= 1;
    }
}

extern "C" void kernel_launch(void* const* d_in, const int* in_sizes, int n_in,
                              void* d_out, int out_size)
{
    (void)in_sizes; (void)n_in; (void)out_size;
    const float* input  = (const float*)d_in[0];
    const float* hidden = (const float*)d_in[1];
    const float* w_i2h  = (const float*)d_in[2];
    const float* b_i2h  = (const float*)d_in[3];
    const float* w_i2o  = (const float*)d_in[4];
    const float* b_i2o  = (const float*)d_in[5];
    float* out = (float*)d_out;

    repack_kernel<<<(NPAIR * PAIR_U32 + 255) / 256, 256>>>(w_i2h, w_i2o);

    cudaFuncSetAttribute(lstm_mma_kernel,
                         cudaFuncAttributeMaxDynamicSharedMemorySize,
                         SMEM_TOTAL);
    lstm_mma_kernel<<<BATCH / MT, THREADS, SMEM_TOTAL>>>(
        input, hidden, b_i2h, b_i2o, out);
}